// round 9
// baseline (speedup 1.0000x reference)
#include <cuda_runtime.h>
#include <cstdint>

#define N_NODES 100000
#define N_EDGES 1600000
#define NHID 64
#define NCLASS 40

// Scratch (static device globals — no allocation)
__device__ float g_agg[N_NODES * NHID];
__device__ float g_h[N_NODES * NHID];

// ---------------------------------------------------------------------------
// float4 copy: agg := src  (implements the "+ x" self term of GIN, eps=0)
// ---------------------------------------------------------------------------
__global__ void copy_kernel(float4* __restrict__ dst, const float4* __restrict__ src, int n4) {
    int i = blockIdx.x * blockDim.x + threadIdx.x;
    if (i < n4) dst[i] = src[i];
}

// ---------------------------------------------------------------------------
// Scatter-add: agg[dst] += feat[src] for every edge.
// 16 threads per edge, one float4 each (contiguous 256B gather burst).
// Vectored f32 reductions (red.global.add.v4.f32) — no read-back, L2-side ALU.
// Edge index dtype (int64 vs int32) detected from high words of first entries.
// ---------------------------------------------------------------------------
__global__ void scatter_kernel(const float* __restrict__ feat,
                               float* __restrict__ agg,
                               const void* __restrict__ ei_raw) {
    int tid = blockIdx.x * blockDim.x + threadIdx.x;
    int e = tid >> 4;
    if (e >= N_EDGES) return;
    int q = tid & 15;

    const long long* ei64 = (const long long*)ei_raw;
    // If the buffer is really int32, each "int64" word packs two indices and
    // its high half is a (almost surely nonzero) node index.
    long long p0 = ei64[0], p1 = ei64[1], p2 = ei64[2];
    bool is64 = ((unsigned long long)p0 < (1ULL << 32)) &&
                ((unsigned long long)p1 < (1ULL << 32)) &&
                ((unsigned long long)p2 < (1ULL << 32));

    int s, d;
    if (is64) {
        s = (int)ei64[e];
        d = (int)ei64[N_EDGES + e];
    } else {
        const int* ei32 = (const int*)ei_raw;
        s = ei32[e];
        d = ei32[N_EDGES + e];
    }

    const float4 v = *reinterpret_cast<const float4*>(feat + (size_t)s * NHID + q * 4);
    float* p = agg + (size_t)d * NHID + q * 4;
    asm volatile("red.global.add.v4.f32 [%0], {%1, %2, %3, %4};"
                 :: "l"(p), "f"(v.x), "f"(v.y), "f"(v.z), "f"(v.w)
                 : "memory");
}

// ---------------------------------------------------------------------------
// out = relu(A @ W + b), A:[n,64], W:[64,64], b:[64]
// Block: 256 threads, tile 256 rows x 64 cols.
// Thread (cg = t>>6, rq = t&63) computes 4 rows x 16 cols -> W smem traffic
// amortized 4x; W reads are warp-uniform broadcasts (cg constant per warp).
// ---------------------------------------------------------------------------
__global__ __launch_bounds__(256) void gemm_relu_kernel(
    const float* __restrict__ A, const float* __restrict__ W,
    const float* __restrict__ b, float* __restrict__ out, int nrows)
{
    __shared__ __align__(16) float Ws[64 * 64];
    __shared__ float bs[64];
    int t = threadIdx.x;

    const float4* Wg = (const float4*)W;
    float4* Wsv = (float4*)Ws;
    #pragma unroll
    for (int i = 0; i < 4; i++) Wsv[t + i * 256] = Wg[t + i * 256];
    if (t < 64) bs[t] = b[t];
    __syncthreads();

    int cg = t >> 6;                        // column group: cols [cg*16, cg*16+16)
    int rq = t & 63;
    int r0 = blockIdx.x * 256 + rq * 4;

    float acc[4][16];
    #pragma unroll
    for (int rr = 0; rr < 4; rr++)
        #pragma unroll
        for (int c = 0; c < 16; c++) acc[rr][c] = 0.f;

    for (int k = 0; k < 64; k += 4) {
        float xv[4][4];
        #pragma unroll
        for (int rr = 0; rr < 4; rr++) {
            int r = r0 + rr;
            float4 v = (r < nrows)
                ? *reinterpret_cast<const float4*>(A + (size_t)r * 64 + k)
                : make_float4(0.f, 0.f, 0.f, 0.f);
            xv[rr][0] = v.x; xv[rr][1] = v.y; xv[rr][2] = v.z; xv[rr][3] = v.w;
        }
        #pragma unroll
        for (int kk = 0; kk < 4; kk++) {
            const float4* wr = reinterpret_cast<const float4*>(Ws + (k + kk) * 64 + cg * 16);
            float w[16];
            #pragma unroll
            for (int j = 0; j < 4; j++) {
                float4 ww = wr[j];
                w[j*4+0] = ww.x; w[j*4+1] = ww.y; w[j*4+2] = ww.z; w[j*4+3] = ww.w;
            }
            #pragma unroll
            for (int rr = 0; rr < 4; rr++) {
                float a = xv[rr][kk];
                #pragma unroll
                for (int c = 0; c < 16; c++) acc[rr][c] += a * w[c];
            }
        }
    }

    #pragma unroll
    for (int rr = 0; rr < 4; rr++) {
        int r = r0 + rr;
        if (r < nrows) {
            float* op = out + (size_t)r * 64 + cg * 16;
            #pragma unroll
            for (int j = 0; j < 4; j++) {
                float4 o;
                o.x = fmaxf(acc[rr][j*4+0] + bs[cg*16 + j*4+0], 0.f);
                o.y = fmaxf(acc[rr][j*4+1] + bs[cg*16 + j*4+1], 0.f);
                o.z = fmaxf(acc[rr][j*4+2] + bs[cg*16 + j*4+2], 0.f);
                o.w = fmaxf(acc[rr][j*4+3] + bs[cg*16 + j*4+3], 0.f);
                *reinterpret_cast<float4*>(op + j * 4) = o;
            }
        }
    }
}

// ---------------------------------------------------------------------------
// out = log_softmax(A @ Wf + bf), A:[n,64], Wf:[64,40]
// 2 rows per thread (halves W smem traffic); logits live in registers so
// log_softmax is fused with no intermediate buffer.
// ---------------------------------------------------------------------------
__global__ __launch_bounds__(256) void final_kernel(
    const float* __restrict__ A, const float* __restrict__ W,
    const float* __restrict__ b, float* __restrict__ out, int nrows)
{
    __shared__ __align__(16) float Ws[64 * NCLASS];
    __shared__ float bs[NCLASS];
    int t = threadIdx.x;
    for (int i = t; i < 64 * NCLASS / 4; i += 256)
        ((float4*)Ws)[i] = ((const float4*)W)[i];
    if (t < NCLASS) bs[t] = b[t];
    __syncthreads();

    int r0 = (blockIdx.x * 256 + t) * 2;

    float acc[2][NCLASS];
    #pragma unroll
    for (int rr = 0; rr < 2; rr++)
        #pragma unroll
        for (int c = 0; c < NCLASS; c++) acc[rr][c] = bs[c];

    for (int k = 0; k < 64; k += 4) {
        float xv[2][4];
        #pragma unroll
        for (int rr = 0; rr < 2; rr++) {
            int r = r0 + rr;
            float4 v = (r < nrows)
                ? *reinterpret_cast<const float4*>(A + (size_t)r * 64 + k)
                : make_float4(0.f, 0.f, 0.f, 0.f);
            xv[rr][0] = v.x; xv[rr][1] = v.y; xv[rr][2] = v.z; xv[rr][3] = v.w;
        }
        #pragma unroll
        for (int kk = 0; kk < 4; kk++) {
            const float4* wr = reinterpret_cast<const float4*>(Ws + (k + kk) * NCLASS);
            #pragma unroll
            for (int c4 = 0; c4 < NCLASS / 4; c4++) {
                float4 ww = wr[c4];
                #pragma unroll
                for (int rr = 0; rr < 2; rr++) {
                    float a = xv[rr][kk];
                    acc[rr][c4*4+0] += a * ww.x;
                    acc[rr][c4*4+1] += a * ww.y;
                    acc[rr][c4*4+2] += a * ww.z;
                    acc[rr][c4*4+3] += a * ww.w;
                }
            }
        }
    }

    #pragma unroll
    for (int rr = 0; rr < 2; rr++) {
        int r = r0 + rr;
        if (r >= nrows) continue;
        float m = acc[rr][0];
        #pragma unroll
        for (int c = 1; c < NCLASS; c++) m = fmaxf(m, acc[rr][c]);
        float s = 0.f;
        #pragma unroll
        for (int c = 0; c < NCLASS; c++) s += __expf(acc[rr][c] - m);
        float lse = m + __logf(s);
        float* op = out + (size_t)r * NCLASS;
        #pragma unroll
        for (int c4 = 0; c4 < NCLASS / 4; c4++) {
            float4 o;
            o.x = acc[rr][c4*4+0] - lse;
            o.y = acc[rr][c4*4+1] - lse;
            o.z = acc[rr][c4*4+2] - lse;
            o.w = acc[rr][c4*4+3] - lse;
            *reinterpret_cast<float4*>(op + c4 * 4) = o;
        }
    }
}

// ---------------------------------------------------------------------------
extern "C" void kernel_launch(void* const* d_in, const int* in_sizes, int n_in,
                              void* d_out, int out_size) {
    const float* x  = (const float*)d_in[0];
    const void*  ei = d_in[1];                 // int64 or int32, detected on device
    const float* W1 = (const float*)d_in[2];
    const float* b1 = (const float*)d_in[3];
    const float* W2 = (const float*)d_in[4];
    const float* b2 = (const float*)d_in[5];
    const float* Wf = (const float*)d_in[6];
    const float* bf = (const float*)d_in[7];
    float* out = (float*)d_out;

    float *agg, *h;
    cudaGetSymbolAddress((void**)&agg, g_agg);
    cudaGetSymbolAddress((void**)&h, g_h);

    const int n4 = N_NODES * NHID / 4;
    const int copy_blocks = (n4 + 255) / 256;
    const int scat_blocks = (N_EDGES * 16 + 255) / 256;
    const int gemm_blocks = (N_NODES + 255) / 256;
    const int fin_blocks  = (N_NODES + 511) / 512;

    // Layer 1: agg = x + sum_{j->i} x_j ; h = relu(agg @ W1 + b1)
    copy_kernel<<<copy_blocks, 256>>>((float4*)agg, (const float4*)x, n4);
    scatter_kernel<<<scat_blocks, 256>>>(x, agg, ei);
    gemm_relu_kernel<<<gemm_blocks, 256>>>(agg, W1, b1, h, N_NODES);

    // Layer 2
    copy_kernel<<<copy_blocks, 256>>>((float4*)agg, (const float4*)h, n4);
    scatter_kernel<<<scat_blocks, 256>>>(h, agg, ei);
    gemm_relu_kernel<<<gemm_blocks, 256>>>(agg, W2, b2, h, N_NODES);

    // Classifier + log_softmax (fused)
    final_kernel<<<fin_blocks, 256>>>(h, Wf, bf, out, N_NODES);
}